// round 2
// baseline (speedup 1.0000x reference)
#include <cuda_runtime.h>
#include <math.h>

#define B_ 4
#define T_ 1024
#define F_ 128
#define D_ 512
#define H_ 8
#define L_ 4
#define DFF_ 2048
#define NE_ 16
#define MD_ 20
#define HD_ 64
#define NT_ (B_*T_)
#define SCALE_ 0.125f

// ---------------- scratch (device globals: no allocations allowed) ----------
__device__ float g_x  [NT_*(size_t)D_];
__device__ float g_q  [NT_*(size_t)D_];
__device__ float g_k  [NT_*(size_t)D_];
__device__ float g_v  [NT_*(size_t)D_];
__device__ float g_o  [NT_*(size_t)D_];
__device__ float g_ffn[NT_*(size_t)DFF_];
__device__ float g_bias  [(size_t)B_*H_*T_*T_];
__device__ float g_scores[(size_t)B_*H_*T_*T_];

// ---------------- helpers ---------------------------------------------------
__device__ __forceinline__ float warp_red_sum(float v) {
    #pragma unroll
    for (int o = 16; o > 0; o >>= 1) v += __shfl_xor_sync(0xffffffffu, v, o);
    return v;
}
__device__ __forceinline__ float warp_red_max(float v) {
    #pragma unroll
    for (int o = 16; o > 0; o >>= 1) v = fmaxf(v, __shfl_xor_sync(0xffffffffu, v, o));
    return v;
}

// ---------------- generic SGEMM: C[M,N] = act(A[M,K] @ W[K,N] + bias) (+resid)
// BM=64, BN=64, BK=16, 256 threads, 4x4 microtile per thread.
#define BM 64
#define BN 64
#define BK 16

template<int ACT, bool RESID>
__global__ __launch_bounds__(256)
void sgemm_kernel(const float* __restrict__ A, const float* __restrict__ W,
                  const float* __restrict__ bias, const float* __restrict__ resid,
                  float* __restrict__ C, int M, int K, int N)
{
    __shared__ float As[BK][BM];      // transposed: As[k][m]
    __shared__ float Ws[BK][BN];      // direct:     Ws[k][n]

    const int t  = threadIdx.x;
    const int m0 = blockIdx.y * BM;
    const int n0 = blockIdx.x * BN;
    const int tx = t & 15;            // 0..15 -> n
    const int ty = t >> 4;            // 0..15 -> m

    const int arow = t >> 2;          // 0..63
    const int aseg = t & 3;           // float4 along K
    const int wrow = t >> 4;          // 0..15 (k)
    const int wseg = t & 15;          // float4 along N

    float acc[4][4] = {};

    for (int k0 = 0; k0 < K; k0 += BK) {
        float4 av = *(const float4*)&A[(size_t)(m0 + arow) * K + k0 + aseg * 4];
        As[aseg*4+0][arow] = av.x;
        As[aseg*4+1][arow] = av.y;
        As[aseg*4+2][arow] = av.z;
        As[aseg*4+3][arow] = av.w;
        float4 wv = *(const float4*)&W[(size_t)(k0 + wrow) * N + n0 + wseg * 4];
        *(float4*)&Ws[wrow][wseg*4] = wv;
        __syncthreads();

        #pragma unroll
        for (int kk = 0; kk < BK; kk++) {
            float4 a4 = *(const float4*)&As[kk][ty*4];
            float4 b4 = *(const float4*)&Ws[kk][tx*4];
            float ar[4] = {a4.x, a4.y, a4.z, a4.w};
            float br[4] = {b4.x, b4.y, b4.z, b4.w};
            #pragma unroll
            for (int i = 0; i < 4; i++)
                #pragma unroll
                for (int j = 0; j < 4; j++)
                    acc[i][j] = fmaf(ar[i], br[j], acc[i][j]);
        }
        __syncthreads();
    }

    #pragma unroll
    for (int i = 0; i < 4; i++) {
        const int m = m0 + ty*4 + i;
        #pragma unroll
        for (int j = 0; j < 4; j++) {
            const int n = n0 + tx*4 + j;
            float v = acc[i][j] + bias[n];
            if (ACT == 1) v = v / (1.0f + __expf(-v));   // SiLU
            if (RESID)    v += resid[(size_t)m * N + n];
            C[(size_t)m * N + n] = v;
        }
    }
}

// ---------------- embedding extras ------------------------------------------
__global__ void add_cent_kernel(float* __restrict__ h, const float* __restrict__ cent,
                                const float* __restrict__ cw, const float* __restrict__ cb)
{
    const int n = blockIdx.x, d = threadIdx.x;
    h[(size_t)n * D_ + d] += cent[n] * cw[d] + cb[d];
}

// bias[b,h,i,j] = edge_emb[et[b,i,j],h] + dist_emb[min(sp,MD),h]
__global__ void bias_kernel(const int* __restrict__ et, const int* __restrict__ sp,
                            const float* __restrict__ ee, const float* __restrict__ de,
                            float* __restrict__ bias)
{
    const size_t tid = (size_t)blockIdx.x * blockDim.x + threadIdx.x;  // B*T*T
    const int e = et[tid];
    int s = sp[tid]; if (s > MD_) s = MD_; if (s < 0) s = 0;
    const size_t j = tid & (T_ - 1);
    const size_t i = (tid >> 10) & (T_ - 1);
    const size_t b = tid >> 20;
    #pragma unroll
    for (int hh = 0; hh < H_; hh++)
        bias[(((b*H_ + hh)*T_ + i)*T_) + j] = ee[e*H_ + hh] + de[s*H_ + hh];
}

// ---------------- layernorm --------------------------------------------------
__global__ __launch_bounds__(128)
void ln_kernel(const float* __restrict__ h, const float* __restrict__ w,
               const float* __restrict__ b, float* __restrict__ out)
{
    __shared__ float red[8];
    const int t = threadIdx.x;                     // 128 threads, 4 elems each
    const float* hp = h + (size_t)blockIdx.x * D_;
    float v[4]; float s = 0.f, s2 = 0.f;
    #pragma unroll
    for (int u = 0; u < 4; u++) { v[u] = hp[t + u*128]; s += v[u]; s2 += v[u]*v[u]; }
    s  = warp_red_sum(s);
    s2 = warp_red_sum(s2);
    if ((t & 31) == 0) { red[t>>5] = s; red[4 + (t>>5)] = s2; }
    __syncthreads();
    s  = red[0] + red[1] + red[2] + red[3];
    s2 = red[4] + red[5] + red[6] + red[7];
    const float m   = s  * (1.0f / D_);
    const float var = s2 * (1.0f / D_) - m * m;
    const float r   = rsqrtf(var + 1e-5f);
    float* op = out + (size_t)blockIdx.x * D_;
    #pragma unroll
    for (int u = 0; u < 4; u++) {
        const int d = t + u*128;
        op[d] = (v[u] - m) * r * w[d] + b[d];
    }
}

// ---------------- attention: scores = scale*Q.K^T + bias --------------------
// grid (T/64, T/64, B*H), 256 threads, 4x4 microtile, K=HD=64 fully resident.
__global__ __launch_bounds__(256)
void scores_kernel(const float* __restrict__ q, const float* __restrict__ k,
                   const float* __restrict__ bias, float* __restrict__ scores)
{
    __shared__ float Qs[64][65];   // [d][i]
    __shared__ float Ks[64][65];   // [d][j]
    const int z  = blockIdx.z;          // b*H + h
    const int b  = z / H_, h = z % H_;
    const int i0 = blockIdx.y * 64, j0 = blockIdx.x * 64;
    const float* qp = q + (size_t)b * T_ * D_ + h * HD_;
    const float* kp = k + (size_t)b * T_ * D_ + h * HD_;
    const int t = threadIdx.x;

    #pragma unroll
    for (int u = 0; u < 4; u++) {
        const int lin = t + u*256;         // 1024 float4 total
        const int row = lin >> 4;          // 0..63
        const int d4  = lin & 15;
        float4 a = *(const float4*)&qp[(size_t)(i0 + row) * D_ + d4*4];
        Qs[d4*4+0][row]=a.x; Qs[d4*4+1][row]=a.y; Qs[d4*4+2][row]=a.z; Qs[d4*4+3][row]=a.w;
        float4 c = *(const float4*)&kp[(size_t)(j0 + row) * D_ + d4*4];
        Ks[d4*4+0][row]=c.x; Ks[d4*4+1][row]=c.y; Ks[d4*4+2][row]=c.z; Ks[d4*4+3][row]=c.w;
    }
    __syncthreads();

    const int tx = t & 15, ty = t >> 4;
    float acc[4][4] = {};
    #pragma unroll 16
    for (int d = 0; d < 64; d++) {
        float ar[4], br[4];
        #pragma unroll
        for (int i = 0; i < 4; i++) ar[i] = Qs[d][ty*4 + i];
        #pragma unroll
        for (int j = 0; j < 4; j++) br[j] = Ks[d][tx*4 + j];
        #pragma unroll
        for (int i = 0; i < 4; i++)
            #pragma unroll
            for (int j = 0; j < 4; j++)
                acc[i][j] = fmaf(ar[i], br[j], acc[i][j]);
    }

    const float* bp = bias   + (size_t)z * T_ * T_;
    float*       sp = scores + (size_t)z * T_ * T_;
    #pragma unroll
    for (int i = 0; i < 4; i++) {
        const int ii = i0 + ty*4 + i;
        #pragma unroll
        for (int j = 0; j < 4; j++) {
            const int jj = j0 + tx*4 + j;
            sp[(size_t)ii * T_ + jj] = acc[i][j] * SCALE_ + bp[(size_t)ii * T_ + jj];
        }
    }
}

// ---------------- softmax over last axis (rows of length T) -----------------
__global__ __launch_bounds__(256)
void softmax_kernel(float* __restrict__ s)
{
    __shared__ float red[8];
    const int t = threadIdx.x;
    float* p = s + (size_t)blockIdx.x * T_;
    float v[4];
    float mx = -1e30f;
    #pragma unroll
    for (int u = 0; u < 4; u++) { v[u] = p[t + u*256]; mx = fmaxf(mx, v[u]); }
    mx = warp_red_max(mx);
    if ((t & 31) == 0) red[t>>5] = mx;
    __syncthreads();
    mx = red[0];
    #pragma unroll
    for (int i = 1; i < 8; i++) mx = fmaxf(mx, red[i]);
    __syncthreads();
    float sum = 0.f;
    #pragma unroll
    for (int u = 0; u < 4; u++) { v[u] = __expf(v[u] - mx); sum += v[u]; }
    sum = warp_red_sum(sum);
    if ((t & 31) == 0) red[t>>5] = sum;
    __syncthreads();
    sum = red[0]+red[1]+red[2]+red[3]+red[4]+red[5]+red[6]+red[7];
    const float inv = 1.0f / sum;
    #pragma unroll
    for (int u = 0; u < 4; u++) p[t + u*256] = v[u] * inv;
}

// ---------------- o = attn @ V ----------------------------------------------
// grid (T/64, 1, B*H): each block computes o tile [64 i][64 d] for one head.
__global__ __launch_bounds__(256)
void av_kernel(const float* __restrict__ attn, const float* __restrict__ v,
               float* __restrict__ o)
{
    __shared__ float As[32][65];   // [j][i]
    __shared__ float Vs[32][65];   // [j][d]
    const int z = blockIdx.z;
    const int b = z / H_, h = z % H_;
    const int i0 = blockIdx.x * 64;
    const float* ap = attn + (size_t)z * T_ * T_;
    const float* vp = v + (size_t)b * T_ * D_ + h * HD_;
    const int t = threadIdx.x;
    const int tx = t & 15, ty = t >> 4;
    float acc[4][4] = {};

    for (int j0 = 0; j0 < T_; j0 += 32) {
        #pragma unroll
        for (int u = 0; u < 2; u++) {
            int lin = t + u*256;               // 512 float4 total
            { // attn tile 64 x 32: row = i (0..63), 8 float4 along j
                const int row = lin >> 3;
                const int j4  = lin & 7;
                float4 a = *(const float4*)&ap[(size_t)(i0 + row) * T_ + j0 + j4*4];
                As[j4*4+0][row]=a.x; As[j4*4+1][row]=a.y; As[j4*4+2][row]=a.z; As[j4*4+3][row]=a.w;
            }
            { // V tile 32 x 64: row = j (0..31), 16 float4 along d
                const int row = lin >> 4;
                const int d4  = lin & 15;
                float4 c = *(const float4*)&vp[(size_t)(j0 + row) * D_ + d4*4];
                Vs[row][d4*4+0]=c.x; Vs[row][d4*4+1]=c.y; Vs[row][d4*4+2]=c.z; Vs[row][d4*4+3]=c.w;
            }
        }
        __syncthreads();
        #pragma unroll 8
        for (int jj = 0; jj < 32; jj++) {
            float ar[4], br[4];
            #pragma unroll
            for (int i = 0; i < 4; i++) ar[i] = As[jj][ty*4 + i];
            #pragma unroll
            for (int d = 0; d < 4; d++) br[d] = Vs[jj][tx*4 + d];
            #pragma unroll
            for (int i = 0; i < 4; i++)
                #pragma unroll
                for (int d = 0; d < 4; d++)
                    acc[i][d] = fmaf(ar[i], br[d], acc[i][d]);
        }
        __syncthreads();
    }

    #pragma unroll
    for (int i = 0; i < 4; i++) {
        const size_t row = (size_t)b * T_ + i0 + ty*4 + i;
        #pragma unroll
        for (int d = 0; d < 4; d++)
            o[row * D_ + h * HD_ + tx*4 + d] = acc[i][d];
    }
}

// ---------------- host-side orchestration -----------------------------------
static inline void gemm(const float* A, const float* W, const float* bias,
                        const float* resid, float* C, int M, int K, int N, int act)
{
    dim3 g(N / BN, M / BM);
    if (act == 1)        sgemm_kernel<1,false><<<g,256>>>(A, W, bias, nullptr, C, M, K, N);
    else if (resid)      sgemm_kernel<0,true ><<<g,256>>>(A, W, bias, resid,  C, M, K, N);
    else                 sgemm_kernel<0,false><<<g,256>>>(A, W, bias, nullptr, C, M, K, N);
}

extern "C" void kernel_launch(void* const* d_in, const int* in_sizes, int n_in,
                              void* d_out, int out_size)
{
    const float* nf     = (const float*)d_in[0];
    const float* cent   = (const float*)d_in[1];
    const int*   et     = (const int*)  d_in[2];
    const int*   sp     = (const int*)  d_in[3];
    const float* node_W = (const float*)d_in[4];
    const float* node_b = (const float*)d_in[5];
    const float* cent_W = (const float*)d_in[6];
    const float* cent_b = (const float*)d_in[7];
    const float* e_emb  = (const float*)d_in[8];
    const float* d_emb  = (const float*)d_in[9];
    const float* ln1w   = (const float*)d_in[10];
    const float* ln1b   = (const float*)d_in[11];
    const float* qW     = (const float*)d_in[12];
    const float* qb     = (const float*)d_in[13];
    const float* kW     = (const float*)d_in[14];
    const float* kb     = (const float*)d_in[15];
    const float* vW     = (const float*)d_in[16];
    const float* vb     = (const float*)d_in[17];
    const float* oW     = (const float*)d_in[18];
    const float* ob     = (const float*)d_in[19];
    const float* ln2w   = (const float*)d_in[20];
    const float* ln2b   = (const float*)d_in[21];
    const float* f1W    = (const float*)d_in[22];
    const float* f1b    = (const float*)d_in[23];
    const float* f2W    = (const float*)d_in[24];
    const float* f2b    = (const float*)d_in[25];

    float* h = (float*)d_out;

    float *px, *pq, *pk, *pv, *po, *pffn, *pbias, *pscores;
    cudaGetSymbolAddress((void**)&px,     g_x);
    cudaGetSymbolAddress((void**)&pq,     g_q);
    cudaGetSymbolAddress((void**)&pk,     g_k);
    cudaGetSymbolAddress((void**)&pv,     g_v);
    cudaGetSymbolAddress((void**)&po,     g_o);
    cudaGetSymbolAddress((void**)&pffn,   g_ffn);
    cudaGetSymbolAddress((void**)&pbias,  g_bias);
    cudaGetSymbolAddress((void**)&pscores,g_scores);

    // embedding: h = nf @ node_W + node_b ; h += cent*cent_W + cent_b
    gemm(nf, node_W, node_b, nullptr, h, NT_, F_, D_, 0);
    add_cent_kernel<<<NT_, D_>>>(h, cent, cent_W, cent_b);

    // Graphormer attention bias (layer-invariant)
    bias_kernel<<<(B_*T_*T_)/256, 256>>>(et, sp, e_emb, d_emb, pbias);

    for (int l = 0; l < L_; l++) {
        const size_t wd = (size_t)l * D_ * D_;
        // x = LN1(h)
        ln_kernel<<<NT_, 128>>>(h, ln1w + l*D_, ln1b + l*D_, px);
        // q,k,v
        gemm(px, qW + wd, qb + l*D_, nullptr, pq, NT_, D_, D_, 0);
        gemm(px, kW + wd, kb + l*D_, nullptr, pk, NT_, D_, D_, 0);
        gemm(px, vW + wd, vb + l*D_, nullptr, pv, NT_, D_, D_, 0);
        // attention
        scores_kernel<<<dim3(T_/64, T_/64, B_*H_), 256>>>(pq, pk, pbias, pscores);
        softmax_kernel<<<B_*H_*T_, 256>>>(pscores);
        av_kernel<<<dim3(T_/64, 1, B_*H_), 256>>>(pscores, pv, po);
        // h += o @ oW + ob
        gemm(po, oW + wd, ob + l*D_, h, h, NT_, D_, D_, 0);
        // FFN
        ln_kernel<<<NT_, 128>>>(h, ln2w + l*D_, ln2b + l*D_, px);
        gemm(px,  f1W + (size_t)l*D_*DFF_, f1b + l*DFF_, nullptr, pffn, NT_, D_,   DFF_, 1);
        gemm(pffn, f2W + (size_t)l*DFF_*D_, f2b + l*D_,  h,       h,    NT_, DFF_, D_,   0);
    }
}

// round 4
// speedup vs baseline: 2.5543x; 2.5543x over previous
#include <cuda_runtime.h>
#include <math.h>
#include <stdint.h>

#define B_ 4
#define T_ 1024
#define F_ 128
#define D_ 512
#define H_ 8
#define L_ 4
#define DFF_ 2048
#define MD_ 20
#define HD_ 64
#define NT_ (B_*T_)
#define SCALE_ 0.125f

// ---------------- scratch (device globals: no allocations allowed) ----------
__device__ float g_x  [NT_*(size_t)D_];
__device__ float g_q  [NT_*(size_t)D_];
__device__ float g_k  [NT_*(size_t)D_];
__device__ float g_v  [NT_*(size_t)D_];
__device__ float g_o  [NT_*(size_t)D_];
__device__ float g_ffn[NT_*(size_t)DFF_];
__device__ float g_bias  [(size_t)B_*H_*T_*T_];
__device__ float g_scores[(size_t)B_*H_*T_*T_];

// ---------------- tf32 helpers ----------------------------------------------
__device__ __forceinline__ float to_tf32(float x) {
    float y; asm("cvt.rna.tf32.f32 %0, %1;" : "=f"(y) : "f"(x)); return y;
}
__device__ __forceinline__ float4 cvt4(float4 v) {
    v.x = to_tf32(v.x); v.y = to_tf32(v.y); v.z = to_tf32(v.z); v.w = to_tf32(v.w);
    return v;
}
// D += A(16x8,row) * B(8x8,col);  A,B hold tf32 bit patterns in fp32 regs.
__device__ __forceinline__ void mma8(float* d, const float* a, const float* b) {
    asm volatile(
      "mma.sync.aligned.m16n8k8.row.col.f32.tf32.tf32.f32 "
      "{%0,%1,%2,%3}, {%4,%5,%6,%7}, {%8,%9}, {%0,%1,%2,%3};\n"
      : "+f"(d[0]), "+f"(d[1]), "+f"(d[2]), "+f"(d[3])
      : "r"(__float_as_uint(a[0])), "r"(__float_as_uint(a[1])),
        "r"(__float_as_uint(a[2])), "r"(__float_as_uint(a[3])),
        "r"(__float_as_uint(b[0])), "r"(__float_as_uint(b[1])));
}

__device__ __forceinline__ float warp_red_sum(float v) {
    #pragma unroll
    for (int o = 16; o > 0; o >>= 1) v += __shfl_xor_sync(0xffffffffu, v, o);
    return v;
}
__device__ __forceinline__ float warp_red_max(float v) {
    #pragma unroll
    for (int o = 16; o > 0; o >>= 1) v = fmaxf(v, __shfl_xor_sync(0xffffffffu, v, o));
    return v;
}

// ---------------- tf32 GEMM: C[M=4096, N] = act(A[M,K] @ W[K,N] + bias) -----
// 128x128x32 block tile, 256 threads, warp tile 64x32 (m16n8k8 frags).
// A smem: [m][36] floats, k index XOR-swizzled by (m&3)<<3  (conflict-free R/W)
// B smem: [k][136] floats                                   (conflict-free R/W)
struct GemmP {
    const float* A;
    const float* W[3];
    const float* bias[3];
    float*       C[3];
    const float* resid;
    int K, N;
};

template<int ACT, bool RESID>
__global__ __launch_bounds__(256)
void gemm_tf32(GemmP p)
{
    __shared__ float As[128*36];
    __shared__ float Bs[32*136];

    const int z = blockIdx.z;
    const float* __restrict__ A    = p.A;
    const float* __restrict__ W    = p.W[z];
    const float* __restrict__ bias = p.bias[z];
    float*       __restrict__ C    = p.C[z];
    const float* __restrict__ resid = p.resid;
    const int K = p.K, N = p.N;
    const int m0 = blockIdx.y * 128, n0 = blockIdx.x * 128;

    const int tid  = threadIdx.x;
    const int warp = tid >> 5, lane = tid & 31;
    const int g  = lane >> 2, qd = lane & 3;
    const int wm = (warp >> 2) * 64;
    const int wn = (warp & 3)  * 32;

    // loaders: A -> 4 float4/thread; B -> 4 float4/thread
    const int a_m  = tid >> 3;     // +32*i
    const int a_k4 = tid & 7;
    const int b_k  = tid >> 5;     // +8*i
    const int b_n4 = tid & 31;

    float4 ra[4], rb[4];
    float acc[4][4][4];
    #pragma unroll
    for (int i = 0; i < 4; i++)
        #pragma unroll
        for (int j = 0; j < 4; j++)
            #pragma unroll
            for (int u = 0; u < 4; u++) acc[i][j][u] = 0.f;

    // prologue load k0 = 0
    #pragma unroll
    for (int i = 0; i < 4; i++)
        ra[i] = *(const float4*)&A[(size_t)(m0 + a_m + 32*i) * K + a_k4*4];
    #pragma unroll
    for (int i = 0; i < 4; i++)
        rb[i] = *(const float4*)&W[(size_t)(b_k + 8*i) * N + n0 + b_n4*4];

    const int nk = K >> 5;
    for (int kt = 0; kt < nk; kt++) {
        // stage current regs -> smem (tf32-converted)
        #pragma unroll
        for (int i = 0; i < 4; i++) {
            const int m = a_m + 32*i;
            *(float4*)&As[m*36 + ((a_k4*4) ^ ((m & 3) << 3))] = cvt4(ra[i]);
        }
        #pragma unroll
        for (int i = 0; i < 4; i++)
            *(float4*)&Bs[(b_k + 8*i)*136 + b_n4*4] = cvt4(rb[i]);
        __syncthreads();

        // prefetch next tile into regs (latency hidden under mma)
        if (kt + 1 < nk) {
            const int k0 = (kt + 1) << 5;
            #pragma unroll
            for (int i = 0; i < 4; i++)
                ra[i] = *(const float4*)&A[(size_t)(m0 + a_m + 32*i) * K + k0 + a_k4*4];
            #pragma unroll
            for (int i = 0; i < 4; i++)
                rb[i] = *(const float4*)&W[(size_t)(k0 + b_k + 8*i) * N + n0 + b_n4*4];
        }

        #pragma unroll
        for (int kk = 0; kk < 4; kk++) {
            const int kb = kk * 8;
            float afr[4][4], bfr[4][2];
            #pragma unroll
            for (int mi = 0; mi < 4; mi++) {
                const int m_ = wm + mi*16 + g;
                const int sw = (m_ & 3) << 3;
                afr[mi][0] = As[ m_     *36 + ((kb + qd    ) ^ sw)];
                afr[mi][1] = As[(m_ + 8)*36 + ((kb + qd    ) ^ sw)];
                afr[mi][2] = As[ m_     *36 + ((kb + qd + 4) ^ sw)];
                afr[mi][3] = As[(m_ + 8)*36 + ((kb + qd + 4) ^ sw)];
            }
            #pragma unroll
            for (int ni = 0; ni < 4; ni++) {
                const int n_ = wn + ni*8 + g;
                bfr[ni][0] = Bs[(kb + qd    )*136 + n_];
                bfr[ni][1] = Bs[(kb + qd + 4)*136 + n_];
            }
            #pragma unroll
            for (int mi = 0; mi < 4; mi++)
                #pragma unroll
                for (int ni = 0; ni < 4; ni++)
                    mma8(acc[mi][ni], afr[mi], bfr[ni]);
        }
        __syncthreads();
    }

    // epilogue
    #pragma unroll
    for (int mi = 0; mi < 4; mi++) {
        const int r0 = m0 + wm + mi*16 + g;
        #pragma unroll
        for (int ni = 0; ni < 4; ni++) {
            const int c0 = n0 + wn + ni*8 + qd*2;
            const float2 bv = *(const float2*)&bias[c0];
            float v0 = acc[mi][ni][0] + bv.x;
            float v1 = acc[mi][ni][1] + bv.y;
            float v2 = acc[mi][ni][2] + bv.x;
            float v3 = acc[mi][ni][3] + bv.y;
            if (ACT == 1) {
                v0 = v0 / (1.0f + __expf(-v0));
                v1 = v1 / (1.0f + __expf(-v1));
                v2 = v2 / (1.0f + __expf(-v2));
                v3 = v3 / (1.0f + __expf(-v3));
            }
            if (RESID) {
                const float2 r1 = *(const float2*)&resid[(size_t)r0 * N + c0];
                const float2 r2 = *(const float2*)&resid[(size_t)(r0 + 8) * N + c0];
                v0 += r1.x; v1 += r1.y; v2 += r2.x; v3 += r2.y;
            }
            *(float2*)&C[(size_t)r0       * N + c0] = make_float2(v0, v1);
            *(float2*)&C[(size_t)(r0 + 8) * N + c0] = make_float2(v2, v3);
        }
    }
}

// ---------------- scores = scale * Q.K^T + bias  (tf32) ---------------------
// block: 64(i) x 64(j) for one (b,h); K = HD = 64 resident in smem.
__global__ __launch_bounds__(256)
void scores_tf32(const float* __restrict__ q, const float* __restrict__ k,
                 const float* __restrict__ bias, float* __restrict__ scores)
{
    __shared__ float Qs[64*68];   // [i][68], d XOR-swizzled by (i&3)<<3
    __shared__ float Ks[64*68];   // [j][68], plain (j-major works as B operand)

    const int z = blockIdx.z;          // b*H + h
    const int b = z >> 3, h = z & 7;
    const int i0 = blockIdx.y * 64, j0 = blockIdx.x * 64;
    const float* qp = q + (size_t)b * T_ * D_ + h * HD_;
    const float* kp = k + (size_t)b * T_ * D_ + h * HD_;

    const int tid = threadIdx.x;
    const int warp = tid >> 5, lane = tid & 31;
    const int g = lane >> 2, qd = lane & 3;
    const int wm = (warp >> 2) * 32;
    const int wn = (warp & 3)  * 16;

    #pragma unroll
    for (int i = 0; i < 4; i++) {
        const int r  = (tid >> 4) + 16*i;
        const int d4 = tid & 15;
        float4 v = cvt4(*(const float4*)&qp[(size_t)(i0 + r) * D_ + d4*4]);
        *(float4*)&Qs[r*68 + ((d4*4) ^ ((r & 3) << 3))] = v;
        float4 w = cvt4(*(const float4*)&kp[(size_t)(j0 + r) * D_ + d4*4]);
        *(float4*)&Ks[r*68 + d4*4] = w;
    }
    __syncthreads();

    float acc[2][2][4];
    #pragma unroll
    for (int i = 0; i < 2; i++)
        #pragma unroll
        for (int j = 0; j < 2; j++)
            #pragma unroll
            for (int u = 0; u < 4; u++) acc[i][j][u] = 0.f;

    #pragma unroll
    for (int kk = 0; kk < 8; kk++) {
        const int kb = kk * 8;
        float afr[2][4], bfr[2][2];
        #pragma unroll
        for (int mi = 0; mi < 2; mi++) {
            const int m_ = wm + mi*16 + g;
            const int sw = (m_ & 3) << 3;
            afr[mi][0] = Qs[ m_     *68 + ((kb + qd    ) ^ sw)];
            afr[mi][1] = Qs[(m_ + 8)*68 + ((kb + qd    ) ^ sw)];
            afr[mi][2] = Qs[ m_     *68 + ((kb + qd + 4) ^ sw)];
            afr[mi][3] = Qs[(m_ + 8)*68 + ((kb + qd + 4) ^ sw)];
        }
        #pragma unroll
        for (int ni = 0; ni < 2; ni++) {
            const int n_ = wn + ni*8 + g;
            bfr[ni][0] = Ks[n_*68 + kb + qd];
            bfr[ni][1] = Ks[n_*68 + kb + qd + 4];
        }
        #pragma unroll
        for (int mi = 0; mi < 2; mi++)
            #pragma unroll
            for (int ni = 0; ni < 2; ni++)
                mma8(acc[mi][ni], afr[mi], bfr[ni]);
    }

    const float* bp = bias   + (size_t)z * T_ * T_;
    float*       sp = scores + (size_t)z * T_ * T_;
    #pragma unroll
    for (int mi = 0; mi < 2; mi++) {
        const int r0 = i0 + wm + mi*16 + g;
        #pragma unroll
        for (int ni = 0; ni < 2; ni++) {
            const int c0 = j0 + wn + ni*8 + qd*2;
            const float2 b1 = *(const float2*)&bp[(size_t)r0       * T_ + c0];
            const float2 b2 = *(const float2*)&bp[(size_t)(r0 + 8) * T_ + c0];
            *(float2*)&sp[(size_t)r0       * T_ + c0] =
                make_float2(acc[mi][ni][0]*SCALE_ + b1.x, acc[mi][ni][1]*SCALE_ + b1.y);
            *(float2*)&sp[(size_t)(r0 + 8) * T_ + c0] =
                make_float2(acc[mi][ni][2]*SCALE_ + b2.x, acc[mi][ni][3]*SCALE_ + b2.y);
        }
    }
}

// ---------------- softmax over rows of length T ------------------------------
__global__ __launch_bounds__(256)
void softmax_kernel(float* __restrict__ s)
{
    __shared__ float red[8];
    const int t = threadIdx.x;
    float* p = s + (size_t)blockIdx.x * T_;
    float v[4];
    float mx = -1e30f;
    #pragma unroll
    for (int u = 0; u < 4; u++) { v[u] = p[t + u*256]; mx = fmaxf(mx, v[u]); }
    mx = warp_red_max(mx);
    if ((t & 31) == 0) red[t >> 5] = mx;
    __syncthreads();
    mx = red[0];
    #pragma unroll
    for (int i = 1; i < 8; i++) mx = fmaxf(mx, red[i]);
    __syncthreads();
    float sum = 0.f;
    #pragma unroll
    for (int u = 0; u < 4; u++) { v[u] = __expf(v[u] - mx); sum += v[u]; }
    sum = warp_red_sum(sum);
    if ((t & 31) == 0) red[t >> 5] = sum;
    __syncthreads();
    sum = red[0]+red[1]+red[2]+red[3]+red[4]+red[5]+red[6]+red[7];
    const float inv = 1.0f / sum;
    #pragma unroll
    for (int u = 0; u < 4; u++) p[t + u*256] = v[u] * inv;
}

// ---------------- o = attn @ V (tf32) ---------------------------------------
// block: 64(i) x 64(d=HD) for one (b,h); loop j in steps of 32.
__global__ __launch_bounds__(256)
void av_tf32(const float* __restrict__ attn, const float* __restrict__ v,
             float* __restrict__ o)
{
    __shared__ float As[64*36];   // P tile [i][36], j-index XOR-swizzled
    __shared__ float Bs[32*72];   // V tile [j][72]

    const int z = blockIdx.z;
    const int b = z >> 3, h = z & 7;
    const int i0 = blockIdx.x * 64;
    const float* ap = attn + (size_t)z * T_ * T_;
    const float* vp = v + (size_t)b * T_ * D_ + h * HD_;

    const int tid = threadIdx.x;
    const int warp = tid >> 5, lane = tid & 31;
    const int g = lane >> 2, qd = lane & 3;
    const int wm = (warp >> 2) * 32;
    const int wn = (warp & 3)  * 16;

    const int a_m  = tid >> 3;     // +32*i  (i<2)
    const int a_k4 = tid & 7;
    const int b_k  = tid >> 4;     // +16*i  (i<2)
    const int b_n4 = tid & 15;

    float4 ra[2], rb[2];
    float acc[2][2][4];
    #pragma unroll
    for (int i = 0; i < 2; i++)
        #pragma unroll
        for (int j = 0; j < 2; j++)
            #pragma unroll
            for (int u = 0; u < 4; u++) acc[i][j][u] = 0.f;

    #pragma unroll
    for (int i = 0; i < 2; i++)
        ra[i] = *(const float4*)&ap[(size_t)(i0 + a_m + 32*i) * T_ + a_k4*4];
    #pragma unroll
    for (int i = 0; i < 2; i++)
        rb[i] = *(const float4*)&vp[(size_t)(b_k + 16*i) * D_ + b_n4*4];

    for (int kt = 0; kt < T_/32; kt++) {
        #pragma unroll
        for (int i = 0; i < 2; i++) {
            const int m = a_m + 32*i;
            *(float4*)&As[m*36 + ((a_k4*4) ^ ((m & 3) << 3))] = cvt4(ra[i]);
        }
        #pragma unroll
        for (int i = 0; i < 2; i++)
            *(float4*)&Bs[(b_k + 16*i)*72 + b_n4*4] = cvt4(rb[i]);
        __syncthreads();

        if (kt + 1 < T_/32) {
            const int j0n = (kt + 1) * 32;
            #pragma unroll
            for (int i = 0; i < 2; i++)
                ra[i] = *(const float4*)&ap[(size_t)(i0 + a_m + 32*i) * T_ + j0n + a_k4*4];
            #pragma unroll
            for (int i = 0; i < 2; i++)
                rb[i] = *(const float4*)&vp[(size_t)(j0n + b_k + 16*i) * D_ + b_n4*4];
        }

        #pragma unroll
        for (int kk = 0; kk < 4; kk++) {
            const int kb = kk * 8;
            float afr[2][4], bfr[2][2];
            #pragma unroll
            for (int mi = 0; mi < 2; mi++) {
                const int m_ = wm + mi*16 + g;
                const int sw = (m_ & 3) << 3;
                afr[mi][0] = As[ m_     *36 + ((kb + qd    ) ^ sw)];
                afr[mi][1] = As[(m_ + 8)*36 + ((kb + qd    ) ^ sw)];
                afr[mi][2] = As[ m_     *36 + ((kb + qd + 4) ^ sw)];
                afr[mi][3] = As[(m_ + 8)*36 + ((kb + qd + 4) ^ sw)];
            }
            #pragma unroll
            for (int ni = 0; ni < 2; ni++) {
                const int n_ = wn + ni*8 + g;
                bfr[ni][0] = Bs[(kb + qd    )*72 + n_];
                bfr[ni][1] = Bs[(kb + qd + 4)*72 + n_];
            }
            #pragma unroll
            for (int mi = 0; mi < 2; mi++)
                #pragma unroll
                for (int ni = 0; ni < 2; ni++)
                    mma8(acc[mi][ni], afr[mi], bfr[ni]);
        }
        __syncthreads();
    }

    #pragma unroll
    for (int mi = 0; mi < 2; mi++) {
        const size_t r0 = (size_t)b * T_ + i0 + wm + mi*16 + g;
        #pragma unroll
        for (int ni = 0; ni < 2; ni++) {
            const int c0 = h * HD_ + wn + ni*8 + qd*2;
            *(float2*)&o[ r0      * D_ + c0] = make_float2(acc[mi][ni][0], acc[mi][ni][1]);
            *(float2*)&o[(r0 + 8) * D_ + c0] = make_float2(acc[mi][ni][2], acc[mi][ni][3]);
        }
    }
}

// ---------------- embedding extras ------------------------------------------
__global__ void add_cent_kernel(float* __restrict__ h, const float* __restrict__ cent,
                                const float* __restrict__ cw, const float* __restrict__ cb)
{
    const int n = blockIdx.x, d = threadIdx.x;
    h[(size_t)n * D_ + d] += cent[n] * cw[d] + cb[d];
}

__global__ void bias_kernel(const int* __restrict__ et, const int* __restrict__ sp,
                            const float* __restrict__ ee, const float* __restrict__ de,
                            float* __restrict__ bias)
{
    const size_t tid = (size_t)blockIdx.x * blockDim.x + threadIdx.x;  // B*T*T
    const int e = et[tid];
    int s = sp[tid]; if (s > MD_) s = MD_; if (s < 0) s = 0;
    const size_t j = tid & (T_ - 1);
    const size_t i = (tid >> 10) & (T_ - 1);
    const size_t b = tid >> 20;
    #pragma unroll
    for (int hh = 0; hh < H_; hh++)
        bias[(((b*H_ + hh)*T_ + i)*T_) + j] = ee[e*H_ + hh] + de[s*H_ + hh];
}

// ---------------- layernorm --------------------------------------------------
__global__ __launch_bounds__(128)
void ln_kernel(const float* __restrict__ h, const float* __restrict__ w,
               const float* __restrict__ b, float* __restrict__ out)
{
    __shared__ float red[8];
    const int t = threadIdx.x;
    const float* hp = h + (size_t)blockIdx.x * D_;
    float v[4]; float s = 0.f, s2 = 0.f;
    #pragma unroll
    for (int u = 0; u < 4; u++) { v[u] = hp[t + u*128]; s += v[u]; s2 += v[u]*v[u]; }
    s  = warp_red_sum(s);
    s2 = warp_red_sum(s2);
    if ((t & 31) == 0) { red[t>>5] = s; red[4 + (t>>5)] = s2; }
    __syncthreads();
    s  = red[0] + red[1] + red[2] + red[3];
    s2 = red[4] + red[5] + red[6] + red[7];
    const float m   = s  * (1.0f / D_);
    const float var = s2 * (1.0f / D_) - m * m;
    const float r   = rsqrtf(var + 1e-5f);
    float* op = out + (size_t)blockIdx.x * D_;
    #pragma unroll
    for (int u = 0; u < 4; u++) {
        const int d = t + u*128;
        op[d] = (v[u] - m) * r * w[d] + b[d];
    }
}

// ---------------- host-side orchestration -----------------------------------
static inline void gemm1(const float* A, const float* W, const float* bias,
                         const float* resid, float* C, int K, int N, int act)
{
    GemmP p;
    p.A = A;
    p.W[0] = p.W[1] = p.W[2] = W;
    p.bias[0] = p.bias[1] = p.bias[2] = bias;
    p.C[0] = p.C[1] = p.C[2] = C;
    p.resid = resid;
    p.K = K; p.N = N;
    dim3 g(N / 128, NT_ / 128, 1);
    if (act == 1)        gemm_tf32<1,false><<<g,256>>>(p);
    else if (resid)      gemm_tf32<0,true ><<<g,256>>>(p);
    else                 gemm_tf32<0,false><<<g,256>>>(p);
}

extern "C" void kernel_launch(void* const* d_in, const int* in_sizes, int n_in,
                              void* d_out, int out_size)
{
    const float* nf     = (const float*)d_in[0];
    const float* cent   = (const float*)d_in[1];
    const int*   et     = (const int*)  d_in[2];
    const int*   sp     = (const int*)  d_in[3];
    const float* node_W = (const float*)d_in[4];
    const float* node_b = (const float*)d_in[5];
    const float* cent_W = (const float*)d_in[6];
    const float* cent_b = (const float*)d_in[7];
    const float* e_emb  = (const float*)d_in[8];
    const float* d_emb  = (const float*)d_in[9];
    const float* ln1w   = (const float*)d_in[10];
    const float* ln1b   = (const float*)d_in[11];
    const float* qW     = (const float*)d_in[12];
    const float* qb     = (const float*)d_in[13];
    const float* kW     = (const float*)d_in[14];
    const float* kb     = (const float*)d_in[15];
    const float* vW     = (const float*)d_in[16];
    const float* vb     = (const float*)d_in[17];
    const float* oW     = (const float*)d_in[18];
    const float* ob     = (const float*)d_in[19];
    const float* ln2w   = (const float*)d_in[20];
    const float* ln2b   = (const float*)d_in[21];
    const float* f1W    = (const float*)d_in[22];
    const float* f1b    = (const float*)d_in[23];
    const float* f2W    = (const float*)d_in[24];
    const float* f2b    = (const float*)d_in[25];

    float* h = (float*)d_out;

    float *px, *pq, *pk, *pv, *po, *pffn, *pbias, *pscores;
    cudaGetSymbolAddress((void**)&px,     g_x);
    cudaGetSymbolAddress((void**)&pq,     g_q);
    cudaGetSymbolAddress((void**)&pk,     g_k);
    cudaGetSymbolAddress((void**)&pv,     g_v);
    cudaGetSymbolAddress((void**)&po,     g_o);
    cudaGetSymbolAddress((void**)&pffn,   g_ffn);
    cudaGetSymbolAddress((void**)&pbias,  g_bias);
    cudaGetSymbolAddress((void**)&pscores,g_scores);

    // embedding: h = nf @ node_W + node_b ; h += cent*cent_W + cent_b
    gemm1(nf, node_W, node_b, nullptr, h, F_, D_, 0);
    add_cent_kernel<<<NT_, D_>>>(h, cent, cent_W, cent_b);

    // Graphormer attention bias (layer-invariant)
    bias_kernel<<<(B_*T_*T_)/256, 256>>>(et, sp, e_emb, d_emb, pbias);

    for (int l = 0; l < L_; l++) {
        const size_t wd = (size_t)l * D_ * D_;
        // x = LN1(h)
        ln_kernel<<<NT_, 128>>>(h, ln1w + l*D_, ln1b + l*D_, px);
        // q,k,v in one batched launch (grid.z = 3)
        {
            GemmP p;
            p.A = px;
            p.W[0] = qW + wd;  p.W[1] = kW + wd;  p.W[2] = vW + wd;
            p.bias[0] = qb + l*D_; p.bias[1] = kb + l*D_; p.bias[2] = vb + l*D_;
            p.C[0] = pq; p.C[1] = pk; p.C[2] = pv;
            p.resid = nullptr;
            p.K = D_; p.N = D_;
            gemm_tf32<0,false><<<dim3(D_/128, NT_/128, 3), 256>>>(p);
        }
        // attention
        scores_tf32<<<dim3(T_/64, T_/64, B_*H_), 256>>>(pq, pk, pbias, pscores);
        softmax_kernel<<<B_*H_*T_, 256>>>(pscores);
        av_tf32<<<dim3(T_/64, 1, B_*H_), 256>>>(pscores, pv, po);
        // h += o @ oW + ob
        gemm1(po, oW + wd, ob + l*D_, h, h, D_, D_, 0);
        // FFN
        ln_kernel<<<NT_, 128>>>(h, ln2w + l*D_, ln2b + l*D_, px);
        gemm1(px,   f1W + (size_t)l*D_*DFF_, f1b + l*DFF_, nullptr, pffn, D_,   DFF_, 1);
        gemm1(pffn, f2W + (size_t)l*DFF_*D_, f2b + l*D_,   h,       h,    DFF_, D_,   0);
    }
}